// round 16
// baseline (speedup 1.0000x reference)
#include <cuda_runtime.h>
#include <cuda_bf16.h>
#include <cstdint>

#define CIN   64
#define COUT  64
#define HH    128
#define WW    128
#define HW    (HH*WW)
#define NB    4
#define NTAP  9
#define THREADS 256

// smem: two A stages (HI+LO each 16KB), two B stages (HI+LO each 8KB), corner buf(48B/px), bias
#define A_ST(s)   ((s) * 32768)
#define A_LO_OFF  16384
#define B_ST(s)   (65536 + (s) * 16384)
#define B_LO_OFF  8192
#define CBUF      98304
#define BIAS_OFF  104448
#define SMEM_BYTES 104704

typedef unsigned long long u64t;

// NHWC scratch: xt[n][p][c]
__device__ float g_xt[(size_t)NB * HW * CIN];
// pre-split, pre-swizzled weights: [tap][hi/lo][2048 u32] = 64 rows x 128B SW128 image
__device__ uint32_t g_wb[NTAP][2][2048];

__device__ __forceinline__ uint32_t smem_u32(const void* p) {
    uint32_t a;
    asm("{ .reg .u64 t; cvta.to.shared.u64 t, %1; cvt.u32.u64 %0, t; }" : "=r"(a) : "l"(p));
    return a;
}
__device__ __forceinline__ u64t fma2(u64t a, u64t b, u64t c) {
    u64t d;
    asm("fma.rn.f32x2 %0, %1, %2, %3;" : "=l"(d) : "l"(a), "l"(b), "l"(c));
    return d;
}
__device__ __forceinline__ u64t mul2(u64t a, u64t b) {
    u64t d;
    asm("mul.rn.f32x2 %0, %1, %2;" : "=l"(d) : "l"(a), "l"(b));
    return d;
}
__device__ __forceinline__ void unpack2(u64t v, float& lo, float& hi) {
    asm("mov.b64 {%0, %1}, %2;" : "=f"(lo), "=f"(hi) : "l"(v));
}
__device__ __forceinline__ void split_pair(float v0, float v1, uint32_t& hi2, uint32_t& lo2) {
    asm("cvt.rn.satfinite.bf16x2.f32 %0, %1, %2;" : "=r"(hi2) : "f"(v1), "f"(v0));
    const float f0 = __uint_as_float(hi2 << 16);
    const float f1 = __uint_as_float(hi2 & 0xFFFF0000u);
    const float r0 = v0 - f0;
    const float r1 = v1 - f1;
    asm("cvt.rn.satfinite.bf16x2.f32 %0, %1, %2;" : "=r"(lo2) : "f"(r1), "f"(r0));
}

#define LDSM4(r0, r1, r2, r3, a) \
    asm volatile("ldmatrix.sync.aligned.m8n8.x4.shared.b16 {%0,%1,%2,%3}, [%4];" \
        : "=r"(r0), "=r"(r1), "=r"(r2), "=r"(r3) : "r"(a))

#define LDSM4T(r0, r1, r2, r3, a) \
    asm volatile("ldmatrix.sync.aligned.m8n8.x4.trans.shared.b16 {%0,%1,%2,%3}, [%4];" \
        : "=r"(r0), "=r"(r1), "=r"(r2), "=r"(r3) : "r"(a))

#define MMA16816(D, a0, a1, a2, a3, b0, b1) \
    asm volatile("mma.sync.aligned.m16n8k16.row.col.f32.bf16.bf16.f32 " \
        "{%0,%1,%2,%3}, {%4,%5,%6,%7}, {%8,%9}, {%0,%1,%2,%3};" \
        : "+f"((D)[0]), "+f"((D)[1]), "+f"((D)[2]), "+f"((D)[3]) \
        : "r"(a0), "r"(a1), "r"(a2), "r"(a3), "r"(b0), "r"(b1))

#define CPASYNC16(s, g) asm volatile("cp.async.cg.shared.global [%0], [%1], 16;" :: "r"(s), "l"(g) : "memory")
#define CPCOMMIT()      asm volatile("cp.async.commit_group;" ::: "memory")
#define CPWAIT0()       asm volatile("cp.async.wait_group 0;" ::: "memory")

struct Corner { int i00, i01, i10, i11; float w00, w01, w10, w11; };

__device__ __forceinline__ Corner make_corner(int ho, int wo, int ky, int kx,
                                              float offy, float offx, float m) {
    Corner r;
    const float py = (float)(ho - 1 + ky) + offy;
    const float px = (float)(wo - 1 + kx) + offx;
    const float fy = floorf(py), fx = floorf(px);
    const float ly = py - fy, lx = px - fx;
    const int y0 = (int)fy, x0 = (int)fx;
    const int y1 = y0 + 1,  x1 = x0 + 1;
    const bool vy0 = (y0 >= 0) & (y0 < HH);
    const bool vy1 = (y1 >= 0) & (y1 < HH);
    const bool vx0 = (x0 >= 0) & (x0 < WW);
    const bool vx1 = (x1 >= 0) & (x1 < WW);
    r.w00 = (vy0 && vx0) ? (1.f - ly) * (1.f - lx) * m : 0.f;
    r.w01 = (vy0 && vx1) ? (1.f - ly) * lx         * m : 0.f;
    r.w10 = (vy1 && vx0) ? ly         * (1.f - lx) * m : 0.f;
    r.w11 = (vy1 && vx1) ? ly         * lx         * m : 0.f;
    const int cy0 = min(max(y0, 0), HH - 1);
    const int cy1 = min(max(y1, 0), HH - 1);
    const int cx0 = min(max(x0, 0), WW - 1);
    const int cx1 = min(max(x1, 0), WW - 1);
    r.i00 = cy0 * WW + cx0;
    r.i01 = cy0 * WW + cx1;
    r.i10 = cy1 * WW + cx0;
    r.i11 = cy1 * WW + cx1;
    return r;
}

// fused prologue: blocks [0, 2048) transpose x; blocks [2048, 2057) split weights
#define TBLOCKS (NB * HW / 32)
__global__ __launch_bounds__(256)
void prep_kernel(const float* __restrict__ x, const float* __restrict__ weight) {
    const int bx  = blockIdx.x;
    const int tid = threadIdx.x;

    if (bx < TBLOCKS) {
        __shared__ float s[32][CIN + 1];
        const int n     = bx >> 9;
        const int pbase = (bx & 511) * 32;
        const float* xn = x + (size_t)n * CIN * HW;
        float* xtn      = g_xt + (size_t)n * HW * CIN;
        #pragma unroll
        for (int it = 0; it < 8; it++) {
            const int idx = it * 256 + tid;
            const int c = idx >> 5;
            const int p = idx & 31;
            s[p][c] = xn[(size_t)c * HW + pbase + p];
        }
        __syncthreads();
        #pragma unroll
        for (int it = 0; it < 8; it++) {
            const int idx = it * 256 + tid;
            const int p = idx >> 6;
            const int c = idx & 63;
            xtn[(size_t)(pbase + p) * CIN + c] = s[p][c];
        }
    } else {
        const int t = bx - TBLOCKS;
        for (int e = tid; e < 64 * 32; e += 256) {
            const int c  = e >> 5;
            const int op = e & 31;
            const int o0 = 2 * op;
            const float v0 = weight[((o0)     * CIN + c) * NTAP + t];
            const float v1 = weight[((o0 + 1) * CIN + c) * NTAP + t];
            uint32_t hi2, lo2;
            split_pair(v0, v1, hi2, lo2);
            const uint32_t byte = (uint32_t)(c * 128 + (((op >> 2) ^ (c & 7)) << 4) + (op & 3) * 4);
            g_wb[t][0][byte >> 2] = hi2;
            g_wb[t][1][byte >> 2] = lo2;
        }
    }
}

__global__ __launch_bounds__(THREADS, 2)
void dcn_mma_kernel(const float* __restrict__ offset,
                    const float* __restrict__ mask,
                    const float* __restrict__ bias,
                    float* __restrict__ out) {
    extern __shared__ char smem[];
    const uint32_t sbase = smem_u32(smem);
    const int tid  = threadIdx.x;
    const int wid  = tid >> 5;
    const int lane = tid & 31;

    const int r0 = blockIdx.x;            // global row ids (n*128 + ho)
    const int r1 = blockIdx.x + 256;

    if (tid < COUT) ((float*)(smem + BIAS_OFF))[tid] = bias[tid];

    const int wp0 = wid * 16;
    const int myp = wp0 + (lane & 15);

    // consumer mapping: warp grid 4 (M) x 2 (N): M=32 rows, N=32 couts per warp
    const int m0    = (wid & 3) * 32;
    const int nbase = (wid >> 2) * 32;
    const uint32_t ngran = (uint32_t)((wid >> 2) * 4);
    const int g8  = lane & 7;
    const int sel = lane >> 3;
    const uint32_t row8  = (uint32_t)(((sel & 1) ? 8 : 0) + g8);
    const uint32_t khalf = (uint32_t)(sel >> 1);

    float d[32];
    #pragma unroll
    for (int i = 0; i < 32; i++) d[i] = 0.f;

    // corner calc for (row r, tap) into cbuf (warp-local); weights pre-duplicated
    auto calc_corners = [&](int r, int tap) {
        const int n  = r >> 7;
        const int ho = r & 127;
        const int ky = tap / 3, kx = tap % 3;
        const float offy = offset[((n * 18 + 2 * tap)     * HH + ho) * WW + myp];
        const float offx = offset[((n * 18 + 2 * tap + 1) * HH + ho) * WW + myp];
        const float m    = mask[((n * 9 + tap) * HH + ho) * WW + myp];
        const Corner c = make_corner(ho, myp, ky, kx, offy, offx, m);
        if (lane < 16) {
            *(int4*)(smem + CBUF + myp * 48)        = make_int4(c.i00, c.i01, c.i10, c.i11);
            *(float4*)(smem + CBUF + myp * 48 + 16) = make_float4(c.w00, c.w00, c.w01, c.w01);
            *(float4*)(smem + CBUF + myp * 48 + 32) = make_float4(c.w10, c.w10, c.w11, c.w11);
        }
        __syncwarp();
    };

    auto stageB = [&](int tap, int st) {
        const uint4* gh = (const uint4*)g_wb[tap][0];
        const uint4* gl = (const uint4*)g_wb[tap][1];
        CPASYNC16(sbase + B_ST(st) + tid * 16,                    (const char*)(gh + tid));
        CPASYNC16(sbase + B_ST(st) + (tid + 256) * 16,            (const char*)(gh + tid + 256));
        CPASYNC16(sbase + B_ST(st) + B_LO_OFF + tid * 16,         (const char*)(gl + tid));
        CPASYNC16(sbase + B_ST(st) + B_LO_OFF + (tid + 256) * 16, (const char*)(gl + tid + 256));
        CPCOMMIT();
    };

    // epilogue for row r (scattered stores, R11-style)
    auto flush_row = [&](int r) {
        const int n  = r >> 7;
        const int ho = r & 127;
        const float* bs = (const float*)(smem + BIAS_OFF);
        float* op = out + (size_t)n * COUT * HW + ho * WW;
        #pragma unroll
        for (int mt = 0; mt < 2; mt++) {
            const int rr = m0 + mt * 16 + (lane >> 2);
            #pragma unroll
            for (int nt = 0; nt < 4; nt++) {
                const int c0 = nbase + nt * 8 + (lane & 3) * 2;
                const float2 bb = *(const float2*)(bs + c0);
                const float* D = d + (mt * 4 + nt) * 4;
                op[c0 * HW + rr]           = D[0] + bb.x;
                op[(c0 + 1) * HW + rr]     = D[1] + bb.y;
                op[c0 * HW + rr + 8]       = D[2] + bb.x;
                op[(c0 + 1) * HW + rr + 8] = D[3] + bb.y;
            }
        }
    };

    // ---- prologue: corners(r0, tap0), B(0) cp.async, produce A(0) ----
    calc_corners(r0, 0);
    stageB(0, 0);
    {
        const float* xtn = g_xt + (size_t)(r0 >> 7) * HW * CIN;
        #pragma unroll
        for (int ck = 0; ck < 4; ck++) {
            u64t v[16];
            #pragma unroll
            for (int j = 0; j < 4; j++) {
                const int px = wp0 + ck * 4 + j;
                const int4 idx = *(const int4*)(smem + CBUF + px * 48);
                v[4 * j + 0] = __ldg((const u64t*)(xtn + (size_t)idx.x * CIN) + lane);
                v[4 * j + 1] = __ldg((const u64t*)(xtn + (size_t)idx.y * CIN) + lane);
                v[4 * j + 2] = __ldg((const u64t*)(xtn + (size_t)idx.z * CIN) + lane);
                v[4 * j + 3] = __ldg((const u64t*)(xtn + (size_t)idx.w * CIN) + lane);
            }
            #pragma unroll
            for (int j = 0; j < 4; j++) {
                const int px = wp0 + ck * 4 + j;
                const u64t* wp = (const u64t*)(smem + CBUF + px * 48 + 16);
                const u64t pv = fma2(wp[3], v[4 * j + 3], fma2(wp[2], v[4 * j + 2],
                                fma2(wp[1], v[4 * j + 1], mul2(wp[0], v[4 * j + 0]))));
                float vx, vy;
                unpack2(pv, vx, vy);
                uint32_t hi2, lo2;
                split_pair(vx, vy, hi2, lo2);
                const uint32_t byte = (uint32_t)(px * 128 + ((((lane >> 2) ^ (px & 7))) << 4) + (lane & 3) * 4);
                *(uint32_t*)(smem + A_ST(0) + byte)            = hi2;
                *(uint32_t*)(smem + A_ST(0) + A_LO_OFF + byte) = lo2;
            }
        }
    }
    CPWAIT0();
    __syncthreads();

    // ---- main pipelined loop: 18 taps (2 rows x 9) ----
    #pragma unroll 1
    for (int tt = 0; tt < 2 * NTAP; tt++) {
        const int s  = tt & 1;
        const int s1 = s ^ 1;
        const bool hasNext = (tt < 2 * NTAP - 1);
        const int tnx = (tt + 1) % NTAP;
        const int rnx = (tt + 1 < NTAP) ? r0 : r1;
        const float* xt_nx = g_xt + (size_t)(rnx >> 7) * HW * CIN;

        if (hasNext) {
            calc_corners(rnx, tnx);
            stageB(tnx, s1);
        }

        const uint32_t aH = sbase + A_ST(s);
        const uint32_t aL = aH + A_LO_OFF;
        const uint32_t bH = sbase + B_ST(s);
        const uint32_t bL = bH + B_LO_OFF;

        #pragma unroll
        for (int ks = 0; ks < 4; ks++) {
            // -- issue gather (4 pixels x 4 corners, all 64 ch) for next tap --
            u64t v[16];
            if (hasNext) {
                #pragma unroll
                for (int j = 0; j < 4; j++) {
                    const int px = wp0 + ks * 4 + j;
                    const int4 idx = *(const int4*)(smem + CBUF + px * 48);
                    v[4 * j + 0] = __ldg((const u64t*)(xt_nx + (size_t)idx.x * CIN) + lane);
                    v[4 * j + 1] = __ldg((const u64t*)(xt_nx + (size_t)idx.y * CIN) + lane);
                    v[4 * j + 2] = __ldg((const u64t*)(xt_nx + (size_t)idx.z * CIN) + lane);
                    v[4 * j + 3] = __ldg((const u64t*)(xt_nx + (size_t)idx.w * CIN) + lane);
                }
            }

            // -- consume k-slice ks (M=32 x N=32 warp tile) --
            {
                const uint32_t aswz = ((uint32_t)(ks * 2) + khalf) ^ (uint32_t)g8;
                uint32_t ah[2][4], al[2][4];
                #pragma unroll
                for (int mt = 0; mt < 2; mt++) {
                    const uint32_t row  = (uint32_t)(m0 + mt * 16) + row8;
                    const uint32_t aoff = row * 128 + (aswz << 4);
                    LDSM4(ah[mt][0], ah[mt][1], ah[mt][2], ah[mt][3], aH + aoff);
                    LDSM4(al[mt][0], al[mt][1], al[mt][2], al[mt][3], aL + aoff);
                }
                const uint32_t brow = (uint32_t)(ks * 16) + row8;
                #pragma unroll
                for (int ntp = 0; ntp < 2; ntp++) {
                    const uint32_t bswz = (ngran + (uint32_t)(ntp * 2) + khalf) ^ (uint32_t)g8;
                    uint32_t b0, b1, b2, b3;
                    LDSM4T(b0, b1, b2, b3, bH + brow * 128 + (bswz << 4));
                    #pragma unroll
                    for (int mt = 0; mt < 2; mt++) {
                        float* D0 = d + (mt * 4 + 2 * ntp) * 4;
                        float* D1 = D0 + 4;
                        MMA16816(D0, ah[mt][0], ah[mt][1], ah[mt][2], ah[mt][3], b0, b1);
                        MMA16816(D1, ah[mt][0], ah[mt][1], ah[mt][2], ah[mt][3], b2, b3);
                        MMA16816(D0, al[mt][0], al[mt][1], al[mt][2], al[mt][3], b0, b1);
                        MMA16816(D1, al[mt][0], al[mt][1], al[mt][2], al[mt][3], b2, b3);
                    }
                    uint32_t c0, c1, c2, c3;
                    LDSM4T(c0, c1, c2, c3, bL + brow * 128 + (bswz << 4));
                    #pragma unroll
                    for (int mt = 0; mt < 2; mt++) {
                        float* D0 = d + (mt * 4 + 2 * ntp) * 4;
                        float* D1 = D0 + 4;
                        MMA16816(D0, ah[mt][0], ah[mt][1], ah[mt][2], ah[mt][3], c0, c1);
                        MMA16816(D1, ah[mt][0], ah[mt][1], ah[mt][2], ah[mt][3], c2, c3);
                    }
                }
            }

            // -- combine (packed f32x2) + STS chunk into stage s1 --
            if (hasNext) {
                #pragma unroll
                for (int j = 0; j < 4; j++) {
                    const int px = wp0 + ks * 4 + j;
                    const u64t* wp = (const u64t*)(smem + CBUF + px * 48 + 16);
                    const u64t pv = fma2(wp[3], v[4 * j + 3], fma2(wp[2], v[4 * j + 2],
                                    fma2(wp[1], v[4 * j + 1], mul2(wp[0], v[4 * j + 0]))));
                    float vx, vy;
                    unpack2(pv, vx, vy);
                    uint32_t hi2, lo2;
                    split_pair(vx, vy, hi2, lo2);
                    const uint32_t byte = (uint32_t)(px * 128 + ((((lane >> 2) ^ (px & 7))) << 4) + (lane & 3) * 4);
                    *(uint32_t*)(smem + A_ST(s1) + byte)            = hi2;
                    *(uint32_t*)(smem + A_ST(s1) + A_LO_OFF + byte) = lo2;
                }
            }
        }

        if (hasNext) CPWAIT0();
        __syncthreads();

        if (tt == NTAP - 1) {
            flush_row(r0);
            #pragma unroll
            for (int i = 0; i < 32; i++) d[i] = 0.f;
        }
    }

    flush_row(r1);
}

extern "C" void kernel_launch(void* const* d_in, const int* in_sizes, int n_in,
                              void* d_out, int out_size) {
    const float* x      = (const float*)d_in[0];
    const float* offset = (const float*)d_in[1];
    const float* mask   = (const float*)d_in[2];
    const float* weight = (const float*)d_in[3];
    const float* bias   = (const float*)d_in[4];
    float* out = (float*)d_out;

    prep_kernel<<<TBLOCKS + NTAP, 256>>>(x, weight);

    cudaFuncSetAttribute(dcn_mma_kernel,
                         cudaFuncAttributeMaxDynamicSharedMemorySize, SMEM_BYTES);
    dcn_mma_kernel<<<NB * HH / 2, THREADS, SMEM_BYTES>>>(offset, mask, bias, out);
}

// round 17
// speedup vs baseline: 1.2102x; 1.2102x over previous
#include <cuda_runtime.h>
#include <cuda_fp16.h>
#include <cstdint>

#define CIN   64
#define COUT  64
#define HH    128
#define WW    128
#define HW    (HH*WW)
#define NB    4
#define NTAP  9
#define THREADS 256

// smem: two A stages (fp16 hi only, 16KB each), two B stages (HI+LO 8KB each), corner buf, bias
#define A_ST(s)   ((s) * 16384)
#define B_ST(s)   (32768 + (s) * 16384)
#define B_LO_OFF  8192
#define CBUF      65536
#define BIAS_OFF  69632
#define SMEM_BYTES 69888

// NHWC scratch: xt[n][p][c]
__device__ float g_xt[(size_t)NB * HW * CIN];
// pre-split fp16, pre-swizzled weights: [tap][hi/lo][2048 u32] = 64 rows x 128B SW128 image
__device__ uint32_t g_wb[NTAP][2][2048];

__device__ __forceinline__ uint32_t smem_u32(const void* p) {
    uint32_t a;
    asm("{ .reg .u64 t; cvta.to.shared.u64 t, %1; cvt.u32.u64 %0, t; }" : "=r"(a) : "l"(p));
    return a;
}

// pack (v0 -> low half, v1 -> high half) fp32 pair to fp16x2
__device__ __forceinline__ uint32_t pack_f16x2(float v0, float v1) {
    uint32_t r;
    asm("cvt.rn.f16x2.f32 %0, %1, %2;" : "=r"(r) : "f"(v1), "f"(v0));
    return r;
}

#define LDSM4(r0, r1, r2, r3, a) \
    asm volatile("ldmatrix.sync.aligned.m8n8.x4.shared.b16 {%0,%1,%2,%3}, [%4];" \
        : "=r"(r0), "=r"(r1), "=r"(r2), "=r"(r3) : "r"(a))

#define LDSM4T(r0, r1, r2, r3, a) \
    asm volatile("ldmatrix.sync.aligned.m8n8.x4.trans.shared.b16 {%0,%1,%2,%3}, [%4];" \
        : "=r"(r0), "=r"(r1), "=r"(r2), "=r"(r3) : "r"(a))

#define MMA16816(D, a0, a1, a2, a3, b0, b1) \
    asm volatile("mma.sync.aligned.m16n8k16.row.col.f32.f16.f16.f32 " \
        "{%0,%1,%2,%3}, {%4,%5,%6,%7}, {%8,%9}, {%0,%1,%2,%3};" \
        : "+f"((D)[0]), "+f"((D)[1]), "+f"((D)[2]), "+f"((D)[3]) \
        : "r"(a0), "r"(a1), "r"(a2), "r"(a3), "r"(b0), "r"(b1))

#define CPASYNC16(s, g) asm volatile("cp.async.cg.shared.global [%0], [%1], 16;" :: "r"(s), "l"(g) : "memory")
#define CPCOMMIT()      asm volatile("cp.async.commit_group;" ::: "memory")
#define CPWAIT0()       asm volatile("cp.async.wait_group 0;" ::: "memory")

struct Corner { int i00, i01, i10, i11; float w00, w01, w10, w11; };

__device__ __forceinline__ Corner make_corner(int ho, int wo, int ky, int kx,
                                              float offy, float offx, float m) {
    Corner r;
    const float py = (float)(ho - 1 + ky) + offy;
    const float px = (float)(wo - 1 + kx) + offx;
    const float fy = floorf(py), fx = floorf(px);
    const float ly = py - fy, lx = px - fx;
    const int y0 = (int)fy, x0 = (int)fx;
    const int y1 = y0 + 1,  x1 = x0 + 1;
    const bool vy0 = (y0 >= 0) & (y0 < HH);
    const bool vy1 = (y1 >= 0) & (y1 < HH);
    const bool vx0 = (x0 >= 0) & (x0 < WW);
    const bool vx1 = (x1 >= 0) & (x1 < WW);
    r.w00 = (vy0 && vx0) ? (1.f - ly) * (1.f - lx) * m : 0.f;
    r.w01 = (vy0 && vx1) ? (1.f - ly) * lx         * m : 0.f;
    r.w10 = (vy1 && vx0) ? ly         * (1.f - lx) * m : 0.f;
    r.w11 = (vy1 && vx1) ? ly         * lx         * m : 0.f;
    const int cy0 = min(max(y0, 0), HH - 1);
    const int cy1 = min(max(y1, 0), HH - 1);
    const int cx0 = min(max(x0, 0), WW - 1);
    const int cx1 = min(max(x1, 0), WW - 1);
    r.i00 = cy0 * WW + cx0;
    r.i01 = cy0 * WW + cx1;
    r.i10 = cy1 * WW + cx0;
    r.i11 = cy1 * WW + cx1;
    return r;
}

// fused prologue: blocks [0, 2048) transpose x; blocks [2048, 2057) split weights (fp16 hi/lo)
#define TBLOCKS (NB * HW / 32)
__global__ __launch_bounds__(256)
void prep_kernel(const float* __restrict__ x, const float* __restrict__ weight) {
    const int bx  = blockIdx.x;
    const int tid = threadIdx.x;

    if (bx < TBLOCKS) {
        __shared__ float s[32][CIN + 1];
        const int n     = bx >> 9;
        const int pbase = (bx & 511) * 32;
        const float* xn = x + (size_t)n * CIN * HW;
        float* xtn      = g_xt + (size_t)n * HW * CIN;
        #pragma unroll
        for (int it = 0; it < 8; it++) {
            const int idx = it * 256 + tid;
            const int c = idx >> 5;
            const int p = idx & 31;
            s[p][c] = xn[(size_t)c * HW + pbase + p];
        }
        __syncthreads();
        #pragma unroll
        for (int it = 0; it < 8; it++) {
            const int idx = it * 256 + tid;
            const int p = idx >> 6;
            const int c = idx & 63;
            xtn[(size_t)(pbase + p) * CIN + c] = s[p][c];
        }
    } else {
        const int t = bx - TBLOCKS;
        for (int e = tid; e < 64 * 32; e += 256) {
            const int c  = e >> 5;
            const int op = e & 31;
            const int o0 = 2 * op;
            const float v0 = weight[((o0)     * CIN + c) * NTAP + t];
            const float v1 = weight[((o0 + 1) * CIN + c) * NTAP + t];
            // fp16 split: h = rn16(v), l = rn16(v - h)
            const float h0 = __half2float(__float2half_rn(v0));
            const float h1 = __half2float(__float2half_rn(v1));
            const uint32_t hi2 = pack_f16x2(h0, h1);
            const uint32_t lo2 = pack_f16x2(v0 - h0, v1 - h1);
            const uint32_t byte = (uint32_t)(c * 128 + (((op >> 2) ^ (c & 7)) << 4) + (op & 3) * 4);
            g_wb[t][0][byte >> 2] = hi2;
            g_wb[t][1][byte >> 2] = lo2;
        }
    }
}

__global__ __launch_bounds__(THREADS, 2)
void dcn_mma_kernel(const float* __restrict__ offset,
                    const float* __restrict__ mask,
                    const float* __restrict__ bias,
                    float* __restrict__ out) {
    extern __shared__ char smem[];
    const uint32_t sbase = smem_u32(smem);
    const int tid  = threadIdx.x;
    const int wid  = tid >> 5;
    const int lane = tid & 31;

    const int n  = blockIdx.x >> 7;
    const int ho = blockIdx.x & 127;

    if (tid < COUT) ((float*)(smem + BIAS_OFF))[tid] = bias[tid];

    const int wp0 = wid * 16;                 // producer: warp's 16 pixels
    const int myp = wp0 + (lane & 15);
    const float* xtn = g_xt + (size_t)n * HW * CIN;

    // consumer mapping: warp grid 4 (M) x 2 (N): M=32 rows, N=32 couts per warp
    const int m0    = (wid & 3) * 32;
    const int nbase = (wid >> 2) * 32;
    const uint32_t ngran = (uint32_t)((wid >> 2) * 4);
    const int g8  = lane & 7;
    const int sel = lane >> 3;
    const uint32_t row8  = (uint32_t)(((sel & 1) ? 8 : 0) + g8);
    const uint32_t khalf = (uint32_t)(sel >> 1);

    float d[32];
    #pragma unroll
    for (int i = 0; i < 32; i++) d[i] = 0.f;

    auto calc_corners = [&](int tt) {
        const int ky = tt / 3, kx = tt % 3;
        const float offy = offset[((n * 18 + 2 * tt)     * HH + ho) * WW + myp];
        const float offx = offset[((n * 18 + 2 * tt + 1) * HH + ho) * WW + myp];
        const float m    = mask[((n * 9 + tt) * HH + ho) * WW + myp];
        const Corner c = make_corner(ho, myp, ky, kx, offy, offx, m);
        if (lane < 16) {
            *(int4*)(smem + CBUF + myp * 32)        = make_int4(c.i00, c.i01, c.i10, c.i11);
            *(float4*)(smem + CBUF + myp * 32 + 16) = make_float4(c.w00, c.w01, c.w10, c.w11);
        }
        __syncwarp();
    };

    // ---- prologue: corners(0), B(0) cp.async, produce A(0) ----
    calc_corners(0);
    {
        const uint4* gh = (const uint4*)g_wb[0][0];
        const uint4* gl = (const uint4*)g_wb[0][1];
        CPASYNC16(sbase + B_ST(0) + tid * 16,                      (const char*)(gh + tid));
        CPASYNC16(sbase + B_ST(0) + (tid + 256) * 16,              (const char*)(gh + tid + 256));
        CPASYNC16(sbase + B_ST(0) + B_LO_OFF + tid * 16,           (const char*)(gl + tid));
        CPASYNC16(sbase + B_ST(0) + B_LO_OFF + (tid + 256) * 16,   (const char*)(gl + tid + 256));
        CPCOMMIT();
    }
    #pragma unroll
    for (int ck = 0; ck < 4; ck++) {
        float2 v[16];
        #pragma unroll
        for (int j = 0; j < 4; j++) {
            const int px = wp0 + ck * 4 + j;
            const int4 idx = *(const int4*)(smem + CBUF + px * 32);
            v[4 * j + 0] = __ldg((const float2*)(xtn + (size_t)idx.x * CIN) + lane);
            v[4 * j + 1] = __ldg((const float2*)(xtn + (size_t)idx.y * CIN) + lane);
            v[4 * j + 2] = __ldg((const float2*)(xtn + (size_t)idx.z * CIN) + lane);
            v[4 * j + 3] = __ldg((const float2*)(xtn + (size_t)idx.w * CIN) + lane);
        }
        #pragma unroll
        for (int j = 0; j < 4; j++) {
            const int px = wp0 + ck * 4 + j;
            const float4 w = *(const float4*)(smem + CBUF + px * 32 + 16);
            float vx = w.x * v[4 * j].x;
            vx = fmaf(w.y, v[4 * j + 1].x, vx);
            vx = fmaf(w.z, v[4 * j + 2].x, vx);
            vx = fmaf(w.w, v[4 * j + 3].x, vx);
            float vy = w.x * v[4 * j].y;
            vy = fmaf(w.y, v[4 * j + 1].y, vy);
            vy = fmaf(w.z, v[4 * j + 2].y, vy);
            vy = fmaf(w.w, v[4 * j + 3].y, vy);
            const uint32_t byte = (uint32_t)(px * 128 + ((((lane >> 2) ^ (px & 7))) << 4) + (lane & 3) * 4);
            *(uint32_t*)(smem + A_ST(0) + byte) = pack_f16x2(vx, vy);
        }
    }
    CPWAIT0();
    __syncthreads();

    // ---- main pipelined loop ----
    #pragma unroll 1
    for (int t = 0; t < NTAP; t++) {
        const int s  = t & 1;
        const int s1 = s ^ 1;
        const bool hasNext = (t < NTAP - 1);

        if (hasNext) {
            calc_corners(t + 1);
            const uint4* gh = (const uint4*)g_wb[t + 1][0];
            const uint4* gl = (const uint4*)g_wb[t + 1][1];
            CPASYNC16(sbase + B_ST(s1) + tid * 16,                    (const char*)(gh + tid));
            CPASYNC16(sbase + B_ST(s1) + (tid + 256) * 16,            (const char*)(gh + tid + 256));
            CPASYNC16(sbase + B_ST(s1) + B_LO_OFF + tid * 16,         (const char*)(gl + tid));
            CPASYNC16(sbase + B_ST(s1) + B_LO_OFF + (tid + 256) * 16, (const char*)(gl + tid + 256));
            CPCOMMIT();
        }

        const uint32_t aH = sbase + A_ST(s);
        const uint32_t bH = sbase + B_ST(s);
        const uint32_t bL = bH + B_LO_OFF;

        #pragma unroll
        for (int ks = 0; ks < 4; ks++) {
            // -- issue gather (4 pixels x 4 corners, all 64 ch) for tap t+1 --
            float2 v[16];
            if (hasNext) {
                #pragma unroll
                for (int j = 0; j < 4; j++) {
                    const int px = wp0 + ks * 4 + j;
                    const int4 idx = *(const int4*)(smem + CBUF + px * 32);
                    v[4 * j + 0] = __ldg((const float2*)(xtn + (size_t)idx.x * CIN) + lane);
                    v[4 * j + 1] = __ldg((const float2*)(xtn + (size_t)idx.y * CIN) + lane);
                    v[4 * j + 2] = __ldg((const float2*)(xtn + (size_t)idx.z * CIN) + lane);
                    v[4 * j + 3] = __ldg((const float2*)(xtn + (size_t)idx.w * CIN) + lane);
                }
            }

            // -- consume k-slice ks of tap t (M=32 x N=32 warp tile, 2-pass fp16) --
            {
                const uint32_t aswz = ((uint32_t)(ks * 2) + khalf) ^ (uint32_t)g8;
                uint32_t ah[2][4];
                #pragma unroll
                for (int mt = 0; mt < 2; mt++) {
                    const uint32_t row  = (uint32_t)(m0 + mt * 16) + row8;
                    const uint32_t aoff = row * 128 + (aswz << 4);
                    LDSM4(ah[mt][0], ah[mt][1], ah[mt][2], ah[mt][3], aH + aoff);
                }
                const uint32_t brow = (uint32_t)(ks * 16) + row8;
                #pragma unroll
                for (int ntp = 0; ntp < 2; ntp++) {
                    const uint32_t bswz = (ngran + (uint32_t)(ntp * 2) + khalf) ^ (uint32_t)g8;
                    uint32_t b0, b1, b2, b3;
                    LDSM4T(b0, b1, b2, b3, bH + brow * 128 + (bswz << 4));
                    #pragma unroll
                    for (int mt = 0; mt < 2; mt++) {
                        float* D0 = d + (mt * 4 + 2 * ntp) * 4;
                        float* D1 = D0 + 4;
                        MMA16816(D0, ah[mt][0], ah[mt][1], ah[mt][2], ah[mt][3], b0, b1);
                        MMA16816(D1, ah[mt][0], ah[mt][1], ah[mt][2], ah[mt][3], b2, b3);
                    }
                    uint32_t c0, c1, c2, c3;
                    LDSM4T(c0, c1, c2, c3, bL + brow * 128 + (bswz << 4));
                    #pragma unroll
                    for (int mt = 0; mt < 2; mt++) {
                        float* D0 = d + (mt * 4 + 2 * ntp) * 4;
                        float* D1 = D0 + 4;
                        MMA16816(D0, ah[mt][0], ah[mt][1], ah[mt][2], ah[mt][3], c0, c1);
                        MMA16816(D1, ah[mt][0], ah[mt][1], ah[mt][2], ah[mt][3], c2, c3);
                    }
                }
            }

            // -- combine + STS chunk into stage s1 --
            if (hasNext) {
                #pragma unroll
                for (int j = 0; j < 4; j++) {
                    const int px = wp0 + ks * 4 + j;
                    const float4 w = *(const float4*)(smem + CBUF + px * 32 + 16);
                    float vx = w.x * v[4 * j].x;
                    vx = fmaf(w.y, v[4 * j + 1].x, vx);
                    vx = fmaf(w.z, v[4 * j + 2].x, vx);
                    vx = fmaf(w.w, v[4 * j + 3].x, vx);
                    float vy = w.x * v[4 * j].y;
                    vy = fmaf(w.y, v[4 * j + 1].y, vy);
                    vy = fmaf(w.z, v[4 * j + 2].y, vy);
                    vy = fmaf(w.w, v[4 * j + 3].y, vy);
                    const uint32_t byte = (uint32_t)(px * 128 + ((((lane >> 2) ^ (px & 7))) << 4) + (lane & 3) * 4);
                    *(uint32_t*)(smem + A_ST(s1) + byte) = pack_f16x2(vx, vy);
                }
            }
        }

        if (hasNext) CPWAIT0();
        __syncthreads();
    }

    // ---- epilogue: warp writes its 32 rows x 32 couts (scattered, R11-style) ----
    const float* bs = (const float*)(smem + BIAS_OFF);
    float* op = out + (size_t)n * COUT * HW + ho * WW;
    #pragma unroll
    for (int mt = 0; mt < 2; mt++) {
        const int r0 = m0 + mt * 16 + (lane >> 2);
        #pragma unroll
        for (int nt = 0; nt < 4; nt++) {
            const int c0 = nbase + nt * 8 + (lane & 3) * 2;
            const float2 bb = *(const float2*)(bs + c0);
            const float* D = d + (mt * 4 + nt) * 4;
            op[c0 * HW + r0]           = D[0] + bb.x;
            op[(c0 + 1) * HW + r0]     = D[1] + bb.y;
            op[c0 * HW + r0 + 8]       = D[2] + bb.x;
            op[(c0 + 1) * HW + r0 + 8] = D[3] + bb.y;
        }
    }
}

extern "C" void kernel_launch(void* const* d_in, const int* in_sizes, int n_in,
                              void* d_out, int out_size) {
    const float* x      = (const float*)d_in[0];
    const float* offset = (const float*)d_in[1];
    const float* mask   = (const float*)d_in[2];
    const float* weight = (const float*)d_in[3];
    const float* bias   = (const float*)d_in[4];
    float* out = (float*)d_out;

    prep_kernel<<<TBLOCKS + NTAP, 256>>>(x, weight);

    cudaFuncSetAttribute(dcn_mma_kernel,
                         cudaFuncAttributeMaxDynamicSharedMemorySize, SMEM_BYTES);
    dcn_mma_kernel<<<NB * HH, THREADS, SMEM_BYTES>>>(offset, mask, bias, out);
}